// round 1
// baseline (speedup 1.0000x reference)
#include <cuda_runtime.h>
#include <math.h>
#include <cfloat>

// ---------------------------------------------------------------------------
// VQGAN forward. Shapes (fixed by the problem):
//  x:  (2,3,64,64,64)
//  enc1: conv k4 s2 p1, 3->64   -> (2,64,32,32,32)  + ReLU
//  enc2: conv k4 s2 p1, 64->128 -> (2,128,16,16,16) + ReLU
//  enc3: conv k4 s2 p1, 128->256-> (2,256,8,8,8)    + ReLU
//  enc4: conv 1x1, 256->256     -> latent (2,256,8,8,8)
//  VQ:   raw-view vectors: lat[b, n, d] = latent_flat[b][n*256+d], n<512
//        argmin_k ( |v|^2 - 2 v.c_k + |c_k|^2 ) over 1024 codes
//        q[b, cd, n] = codebook[idx[b,n]][cd]
//  dec1: convT k4 s2 p1, 256->256 -> (2,256,16,16,16) + ReLU
//  dec2: convT k4 s2 p1, 256->128 -> (2,128,32,32,32) + ReLU
//  dec3: convT k4 s2 p1, 128->64  -> (2,64,64,64,64)  + ReLU
//  dec4: conv k4 s1 p0, 64->3     -> (2,3,61,61,61)   + tanh
// Output buffer: [recon (1361886 f32)] [+ idx (1024) as float if room]
// ---------------------------------------------------------------------------

#define NB 2

// Scratch (static device arrays; no allocations).
__device__ float g_h1[(size_t)NB * 64 * 32 * 32 * 32];    // 4.19M
__device__ float g_h2[(size_t)NB * 128 * 16 * 16 * 16];   // 1.05M
__device__ float g_h3[(size_t)NB * 256 * 8 * 8 * 8];      // 262K
__device__ float g_lat[(size_t)NB * 256 * 512];           // 262K
__device__ float g_q[(size_t)NB * 256 * 512];             // 262K
__device__ float g_d1[(size_t)NB * 256 * 16 * 16 * 16];   // 2.10M
__device__ float g_d2[(size_t)NB * 128 * 32 * 32 * 32];   // 8.39M
__device__ float g_d3[(size_t)NB * 64 * 64 * 64 * 64];    // 33.55M

// ---------------------------------------------------------------------------
// conv3d k=4 s=2 p=1 + ReLU.  Thread: 8 couts x 4 consecutive x-outputs.
// Block: 128 threads -> 512 flat spatial positions, one 8-cout group.
// ---------------------------------------------------------------------------
template <int Cin, int Cout, int Dout>
__global__ void conv_s2_relu(const float* __restrict__ in,
                             const float* __restrict__ w,
                             const float* __restrict__ bias,
                             float* __restrict__ out)
{
    constexpr int Din = 2 * Dout;
    constexpr int CI_CHUNK = (Cin < 16) ? Cin : 16;
    __shared__ float ws[CI_CHUNK][8][64];

    const int tid = threadIdx.x;
    const int coBase = blockIdx.y * 8;
    const int b = blockIdx.z;
    const int s0 = blockIdx.x * 512 + tid * 4;   // Dout%4==0 -> same row
    const int ox0 = s0 % Dout;
    const int oy = (s0 / Dout) % Dout;
    const int oz = s0 / (Dout * Dout);

    float acc[4][8];
#pragma unroll
    for (int p = 0; p < 4; p++)
#pragma unroll
        for (int c = 0; c < 8; c++) acc[p][c] = 0.f;

    const float* inB = in + (size_t)b * Cin * Din * Din * Din;

    for (int ci0 = 0; ci0 < Cin; ci0 += CI_CHUNK) {
        const int nload = CI_CHUNK * 8 * 64;
        for (int i = tid; i < nload; i += 128) {
            int ci = i / (8 * 64);
            int rem = i % (8 * 64);
            int co = rem / 64;
            int tap = rem % 64;
            ws[ci][co][tap] = w[((size_t)(coBase + co) * Cin + (ci0 + ci)) * 64 + tap];
        }
        __syncthreads();

#pragma unroll 1
        for (int ci = 0; ci < CI_CHUNK; ci++) {
            const float* inC = inB + (size_t)(ci0 + ci) * Din * Din * Din;
#pragma unroll
            for (int kd = 0; kd < 4; kd++) {
                const int iz = 2 * oz + kd - 1;
                if ((unsigned)iz >= (unsigned)Din) continue;
#pragma unroll
                for (int kh = 0; kh < 4; kh++) {
                    const int iy = 2 * oy + kh - 1;
                    if ((unsigned)iy >= (unsigned)Din) continue;
                    const float* row = inC + (size_t)iz * Din * Din + (size_t)iy * Din;
#pragma unroll
                    for (int kw = 0; kw < 4; kw++) {
                        const int ixb = 2 * ox0 + kw - 1;
                        float v[4];
#pragma unroll
                        for (int p = 0; p < 4; p++) {
                            int ix = ixb + 2 * p;
                            v[p] = ((unsigned)ix < (unsigned)Din) ? row[ix] : 0.f;
                        }
                        const int tap = kd * 16 + kh * 4 + kw;
#pragma unroll
                        for (int c = 0; c < 8; c++) {
                            float wv = ws[ci][c][tap];
#pragma unroll
                            for (int p = 0; p < 4; p++) acc[p][c] += v[p] * wv;
                        }
                    }
                }
            }
        }
        __syncthreads();
    }

#pragma unroll
    for (int c = 0; c < 8; c++) {
        float bv = bias[coBase + c];
        size_t base = (((size_t)b * Cout + coBase + c) * Dout + oz) * Dout * Dout
                      + (size_t)oy * Dout + ox0;
#pragma unroll
        for (int p = 0; p < 4; p++) out[base + p] = fmaxf(acc[p][c] + bv, 0.f);
    }
}

// ---------------------------------------------------------------------------
// 1x1 conv (enc4): 256 -> 256 over 512 spatial, per batch. No ReLU.
// ---------------------------------------------------------------------------
__global__ void conv1x1(const float* __restrict__ in, const float* __restrict__ w,
                        const float* __restrict__ bias, float* __restrict__ out)
{
    __shared__ float ws[8][256];
    const int tid = threadIdx.x;
    const int coBase = blockIdx.y * 8;
    const int b = blockIdx.z;
    const int s = blockIdx.x * 128 + tid;

    for (int i = tid; i < 8 * 256; i += 128)
        ws[i / 256][i % 256] = w[(size_t)(coBase + i / 256) * 256 + (i % 256)];
    __syncthreads();

    float acc[8];
#pragma unroll
    for (int c = 0; c < 8; c++) acc[c] = 0.f;

    const float* inB = in + (size_t)b * 256 * 512 + s;
    for (int ci = 0; ci < 256; ci++) {
        float v = inB[(size_t)ci * 512];
#pragma unroll
        for (int c = 0; c < 8; c++) acc[c] += v * ws[c][ci];
    }
#pragma unroll
    for (int c = 0; c < 8; c++)
        out[((size_t)b * 256 + coBase + c) * 512 + s] = acc[c] + bias[coBase + c];
}

// ---------------------------------------------------------------------------
// VQ: block handles 8 vectors; 128 threads; thread scans 8 codes (tid+128j).
// Exact expand-norm formula; strict < and smaller-k tie-break (argmin semantics).
// Also writes q (transposed gather) and float idx to output tail.
// ---------------------------------------------------------------------------
__global__ void vq_kernel(const float* __restrict__ lat, const float* __restrict__ cb,
                          float* __restrict__ q, float* __restrict__ idx_out)
{
    __shared__ float4 latS[8][64];
    __shared__ float ln[8];
    __shared__ float bd[8][128];
    __shared__ int bk[8][128];
    __shared__ int wink[8];

    const int tid = threadIdx.x;
    const int vb = blockIdx.x * 8;   // global vector index base (0..1023)

    for (int i = tid; i < 8 * 64; i += 128) {
        int v = i >> 6, d4 = i & 63;
        latS[v][d4] = ((const float4*)lat)[(size_t)(vb + v) * 64 + d4];
    }
    __syncthreads();

    if (tid < 8) {
        float s = 0.f;
        for (int d4 = 0; d4 < 64; d4++) {
            float4 l = latS[tid][d4];
            s += l.x * l.x + l.y * l.y + l.z * l.z + l.w * l.w;
        }
        ln[tid] = s;
    }
    __syncthreads();

    float best[8];
    int bestk[8];
#pragma unroll
    for (int v = 0; v < 8; v++) { best[v] = FLT_MAX; bestk[v] = 0; }

    for (int j = 0; j < 8; j++) {
        const int k = tid + j * 128;
        const float4* cbr = (const float4*)(cb + (size_t)k * 256);
        float dot[8];
        float cn = 0.f;
#pragma unroll
        for (int v = 0; v < 8; v++) dot[v] = 0.f;
        for (int d4 = 0; d4 < 64; d4++) {
            float4 c = cbr[d4];
            cn += c.x * c.x + c.y * c.y + c.z * c.z + c.w * c.w;
#pragma unroll
            for (int v = 0; v < 8; v++) {
                float4 l = latS[v][d4];
                dot[v] += c.x * l.x + c.y * l.y + c.z * l.z + c.w * l.w;
            }
        }
#pragma unroll
        for (int v = 0; v < 8; v++) {
            float d2 = ln[v] - 2.f * dot[v] + cn;
            if (d2 < best[v]) { best[v] = d2; bestk[v] = k; }
        }
    }

#pragma unroll
    for (int v = 0; v < 8; v++) { bd[v][tid] = best[v]; bk[v][tid] = bestk[v]; }
    __syncthreads();
    for (int s = 64; s > 0; s >>= 1) {
        if (tid < s) {
#pragma unroll
            for (int v = 0; v < 8; v++) {
                float dB = bd[v][tid + s];
                int kB = bk[v][tid + s];
                float dA = bd[v][tid];
                int kA = bk[v][tid];
                if (dB < dA || (dB == dA && kB < kA)) { bd[v][tid] = dB; bk[v][tid] = kB; }
            }
        }
        __syncthreads();
    }
    if (tid < 8) {
        wink[tid] = bk[tid][0];
        if (idx_out) idx_out[vb + tid] = (float)bk[tid][0];
    }
    __syncthreads();

    // q[b, c, n] = cb[win][c]
    for (int i = tid; i < 8 * 256; i += 128) {
        int v = i >> 8, c = i & 255;
        int gn = vb + v;
        int b = gn >> 9, n = gn & 511;
        q[((size_t)b * 256 + c) * 512 + n] = cb[(size_t)wink[v] * 256 + c];
    }
}

// ---------------------------------------------------------------------------
// convtranspose3d k=4 s=2 p=1 + ReLU, decomposed into 8 output-parity classes.
// Per class each output is a uniform 2x2x2-tap stride-1 conv:
//   r=0: (k=1, moff=0), (k=3, moff=-1)   r=1: (k=2, moff=0), (k=0, moff=+1)
// Thread: 8 couts x 4 consecutive m-x positions. gridDim.z = B*8 (class).
// Weight layout (torch convT): w[ci][co][kd][kh][kw].
// ---------------------------------------------------------------------------
template <int Cin, int Cout, int Din>
__global__ void convT_relu(const float* __restrict__ in, const float* __restrict__ w,
                           const float* __restrict__ bias, float* __restrict__ out)
{
    constexpr int Dout = 2 * Din;
    constexpr int CI_CHUNK = 16;   // Cin is 256/256/128, multiple of 16
    __shared__ float ws[CI_CHUNK][8][8];

    const int tid = threadIdx.x;
    const int coBase = blockIdx.y * 8;
    const int bz = blockIdx.z;
    const int b = bz >> 3;
    const int cls = bz & 7;
    const int rz = (cls >> 2) & 1, ry = (cls >> 1) & 1, rx = cls & 1;

    int kdt[2], zoff[2], kht[2], yoff[2], kwt[2], xoff[2];
    if (rz == 0) { kdt[0] = 1; zoff[0] = 0; kdt[1] = 3; zoff[1] = -1; }
    else         { kdt[0] = 2; zoff[0] = 0; kdt[1] = 0; zoff[1] = 1; }
    if (ry == 0) { kht[0] = 1; yoff[0] = 0; kht[1] = 3; yoff[1] = -1; }
    else         { kht[0] = 2; yoff[0] = 0; kht[1] = 0; yoff[1] = 1; }
    if (rx == 0) { kwt[0] = 1; xoff[0] = 0; kwt[1] = 3; xoff[1] = -1; }
    else         { kwt[0] = 2; xoff[0] = 0; kwt[1] = 0; xoff[1] = 1; }

    int wtap[8];
#pragma unroll
    for (int tz = 0; tz < 2; tz++)
#pragma unroll
        for (int ty = 0; ty < 2; ty++)
#pragma unroll
            for (int tx = 0; tx < 2; tx++)
                wtap[tz * 4 + ty * 2 + tx] = kdt[tz] * 16 + kht[ty] * 4 + kwt[tx];

    const int m0 = blockIdx.x * 512 + tid * 4;
    const int mx0 = m0 % Din;
    const int my = (m0 / Din) % Din;
    const int mz = m0 / (Din * Din);

    float acc[4][8];
#pragma unroll
    for (int p = 0; p < 4; p++)
#pragma unroll
        for (int c = 0; c < 8; c++) acc[p][c] = 0.f;

    const float* inB = in + (size_t)b * Cin * Din * Din * Din;

    for (int ci0 = 0; ci0 < Cin; ci0 += CI_CHUNK) {
        for (int i = tid; i < CI_CHUNK * 64; i += 128) {
            int ci = i / 64;
            int rem = i % 64;
            int co = rem / 8;
            int t = rem % 8;
            ws[ci][co][t] = w[((size_t)(ci0 + ci) * Cout + coBase + co) * 64 + wtap[t]];
        }
        __syncthreads();

#pragma unroll 1
        for (int ci = 0; ci < CI_CHUNK; ci++) {
            const float* inC = inB + (size_t)(ci0 + ci) * Din * Din * Din;
#pragma unroll
            for (int tz = 0; tz < 2; tz++) {
                const int iz = mz + zoff[tz];
                if ((unsigned)iz >= (unsigned)Din) continue;
#pragma unroll
                for (int ty = 0; ty < 2; ty++) {
                    const int iy = my + yoff[ty];
                    if ((unsigned)iy >= (unsigned)Din) continue;
                    const float* row = inC + (size_t)iz * Din * Din + (size_t)iy * Din;
#pragma unroll
                    for (int tx = 0; tx < 2; tx++) {
                        float v[4];
#pragma unroll
                        for (int p = 0; p < 4; p++) {
                            int ix = mx0 + p + xoff[tx];
                            v[p] = ((unsigned)ix < (unsigned)Din) ? row[ix] : 0.f;
                        }
                        const int t = tz * 4 + ty * 2 + tx;
#pragma unroll
                        for (int c = 0; c < 8; c++) {
                            float wv = ws[ci][c][t];
#pragma unroll
                            for (int p = 0; p < 4; p++) acc[p][c] += v[p] * wv;
                        }
                    }
                }
            }
        }
        __syncthreads();
    }

    const int oz = 2 * mz + rz;
    const int oy = 2 * my + ry;
#pragma unroll
    for (int c = 0; c < 8; c++) {
        float bv = bias[coBase + c];
        size_t base = (((size_t)b * Cout + coBase + c) * Dout + oz) * Dout * Dout
                      + (size_t)oy * Dout;
#pragma unroll
        for (int p = 0; p < 4; p++) {
            int ox = 2 * (mx0 + p) + rx;
            out[base + ox] = fmaxf(acc[p][c] + bv, 0.f);
        }
    }
}

// ---------------------------------------------------------------------------
// dec4: conv3d k=4 s=1 p=0, 64->3, + tanh.  (2,64,64^3) -> (2,3,61^3).
// Thread: 3 couts x 4 consecutive x. Block: 8 y-rows at one z. Weights in smem.
// ---------------------------------------------------------------------------
__global__ void conv_final_tanh(const float* __restrict__ in, const float* __restrict__ w,
                                const float* __restrict__ bias, float* __restrict__ out)
{
    __shared__ float ws[3 * 64 * 64];   // 48KB
    const int tid = threadIdx.x;
    for (int i = tid; i < 3 * 64 * 64; i += 128) ws[i] = w[i];
    __syncthreads();

    const int b = blockIdx.z;
    const int z = blockIdx.y;           // 0..60
    const int ry = tid / 16;            // 0..7
    const int quad = tid % 16;          // 0..15
    const int y = blockIdx.x * 8 + ry;  // 0..63
    const int x0 = quad * 4;            // 0..60
    if (y >= 61) return;

    float acc[3][4];
#pragma unroll
    for (int c = 0; c < 3; c++)
#pragma unroll
        for (int p = 0; p < 4; p++) acc[c][p] = 0.f;

    const float* inB = in + (size_t)b * 64 * 64 * 64 * 64;
#pragma unroll 1
    for (int ci = 0; ci < 64; ci++) {
        const float* inC = inB + (size_t)ci * 262144;
#pragma unroll
        for (int kd = 0; kd < 4; kd++) {
            const float* pz = inC + (size_t)(z + kd) * 4096;
#pragma unroll
            for (int kh = 0; kh < 4; kh++) {
                const float* row = pz + (size_t)(y + kh) * 64;
                float v[7];
#pragma unroll
                for (int j = 0; j < 7; j++) {
                    int ix = x0 + j;
                    v[j] = (ix < 64) ? row[ix] : 0.f;
                }
#pragma unroll
                for (int kw = 0; kw < 4; kw++) {
#pragma unroll
                    for (int c = 0; c < 3; c++) {
                        float wv = ws[((size_t)c * 64 + ci) * 64 + kd * 16 + kh * 4 + kw];
#pragma unroll
                        for (int p = 0; p < 4; p++) acc[c][p] += v[kw + p] * wv;
                    }
                }
            }
        }
    }

#pragma unroll
    for (int c = 0; c < 3; c++) {
        float bv = bias[c];
        size_t base = (((size_t)b * 3 + c) * 61 + z) * 61 * 61 + (size_t)y * 61;
#pragma unroll
        for (int p = 0; p < 4; p++) {
            int x = x0 + p;
            if (x < 61) out[base + x] = tanhf(acc[c][p] + bv);
        }
    }
}

// ---------------------------------------------------------------------------

extern "C" void kernel_launch(void* const* d_in, const int* in_sizes, int n_in,
                              void* d_out, int out_size)
{
    const float* x   = (const float*)d_in[0];
    const float* ew1 = (const float*)d_in[1];  const float* eb1 = (const float*)d_in[2];
    const float* ew2 = (const float*)d_in[3];  const float* eb2 = (const float*)d_in[4];
    const float* ew3 = (const float*)d_in[5];  const float* eb3 = (const float*)d_in[6];
    const float* ew4 = (const float*)d_in[7];  const float* eb4 = (const float*)d_in[8];
    const float* cb  = (const float*)d_in[9];
    const float* dw1 = (const float*)d_in[10]; const float* db1 = (const float*)d_in[11];
    const float* dw2 = (const float*)d_in[12]; const float* db2 = (const float*)d_in[13];
    const float* dw3 = (const float*)d_in[14]; const float* db3 = (const float*)d_in[15];
    const float* dw4 = (const float*)d_in[16]; const float* db4 = (const float*)d_in[17];

    float* out = (float*)d_out;
    const int RECON = 2 * 3 * 61 * 61 * 61;  // 1361886
    float* idx_out = (out_size >= RECON + 1024) ? (out + RECON) : nullptr;

    float *h1, *h2, *h3, *lat, *q, *d1, *d2, *d3;
    cudaGetSymbolAddress((void**)&h1, g_h1);
    cudaGetSymbolAddress((void**)&h2, g_h2);
    cudaGetSymbolAddress((void**)&h3, g_h3);
    cudaGetSymbolAddress((void**)&lat, g_lat);
    cudaGetSymbolAddress((void**)&q, g_q);
    cudaGetSymbolAddress((void**)&d1, g_d1);
    cudaGetSymbolAddress((void**)&d2, g_d2);
    cudaGetSymbolAddress((void**)&d3, g_d3);

    // encoder
    conv_s2_relu<3, 64, 32><<<dim3(64, 8, 2), 128>>>(x, ew1, eb1, h1);
    conv_s2_relu<64, 128, 16><<<dim3(8, 16, 2), 128>>>(h1, ew2, eb2, h2);
    conv_s2_relu<128, 256, 8><<<dim3(1, 32, 2), 128>>>(h2, ew3, eb3, h3);
    conv1x1<<<dim3(4, 32, 2), 128>>>(h3, ew4, eb4, lat);

    // vector quantization (also writes idx tail of output)
    vq_kernel<<<128, 128>>>(lat, cb, q, idx_out);

    // decoder
    convT_relu<256, 256, 8><<<dim3(1, 32, 16), 128>>>(q, dw1, db1, d1);
    convT_relu<256, 128, 16><<<dim3(8, 16, 16), 128>>>(d1, dw2, db2, d2);
    convT_relu<128, 64, 32><<<dim3(64, 8, 16), 128>>>(d2, dw3, db3, d3);
    conv_final_tanh<<<dim3(8, 61, 2), 128>>>(d3, dw4, db4, out);
}